// round 10
// baseline (speedup 1.0000x reference)
#include <cuda_runtime.h>
#include <cuda_fp16.h>
#include <cstdint>
#include <math.h>

#define Nn 4096
#define Ff 256
#define Dd 64
#define Hh 4
#define HD 256
#define NW 128            // adj bitmask words per row (4096/32)
#define LALPHA 0.2f

// ---------------- scratch (device globals; no allocation) ----------------
__device__ __align__(16) float g_h1[Nn * HD];         // layer-1 output [N][H*D]
__device__ __align__(16) __half g_hTh[Hh * Dd * Nn];  // fp16 hi of h, transposed [H][D][N]
__device__ __align__(16) __half g_hTl[Hh * Dd * Nn];  // fp16 residual lo [H][D][N]
__device__ __align__(16) float g_f1[Hh * Nn];
__device__ __align__(16) float g_f2[Hh * Nn];
__device__ __align__(16) float g_G1[Hh * Nn];
__device__ __align__(16) float g_G1p[Hh * Nn];
__device__ __align__(16) float4 g_pk[Hh * Nn];        // (f2, e^f2, e^{a*f2}, _)
__device__ unsigned g_f2maxbits[2 * Hh];
__device__ unsigned g_adjp[Nn * NW];                  // packed adjacency bits

// ---------------- helpers ----------------
static __device__ __forceinline__ uint32_t smem_u32(const void* p) {
    uint32_t a;
    asm("{ .reg .u64 t; cvta.to.shared.u64 t, %1; cvt.u32.u64 %0, t; }" : "=r"(a) : "l"(p));
    return a;
}

static __device__ __forceinline__ uint32_t fkey(float x) {
    unsigned b = __float_as_uint(x);
    return (b & 0x80000000u) ? ~b : (b | 0x80000000u);
}
static __device__ __forceinline__ float fdec(unsigned k) {
    unsigned b = (k & 0x80000000u) ? (k & 0x7FFFFFFFu) : ~k;
    return __uint_as_float(b);
}

static __device__ __forceinline__ uint32_t u32h2(__half2 p) {
    return *reinterpret_cast<uint32_t*>(&p);
}

#define LDSM4(R, addr) \
    asm volatile("ldmatrix.sync.aligned.m8n8.x4.shared.b16 {%0,%1,%2,%3}, [%4];" \
                 : "=r"((R)[0]), "=r"((R)[1]), "=r"((R)[2]), "=r"((R)[3]) : "r"(addr))

#define MMA16816(C, A, B0, B1) \
    asm volatile("mma.sync.aligned.m16n8k16.row.col.f32.f16.f16.f32 " \
                 "{%0,%1,%2,%3}, {%4,%5,%6,%7}, {%8,%9}, {%0,%1,%2,%3};" \
                 : "+f"((C)[0]), "+f"((C)[1]), "+f"((C)[2]), "+f"((C)[3]) \
                 : "r"((A)[0]), "r"((A)[1]), "r"((A)[2]), "r"((A)[3]), "r"(B0), "r"(B1))

#define CP16(dst, src) \
    asm volatile("cp.async.ca.shared.global [%0], [%1], 16;" :: "r"(dst), "l"(src))
#define CP_COMMIT() asm volatile("cp.async.commit_group;")
#define CP_WAIT0()  asm volatile("cp.async.wait_group 0;")

// =====================================================================
// K0: pack adjacency into bitmask (+ reset f2max atomics)
// =====================================================================
__global__ void pack_adj_kernel(const int* __restrict__ adj)
{
    if (blockIdx.x == 0 && threadIdx.x < 2 * Hh) g_f2maxbits[threadIdx.x] = 0u;
    int w = blockIdx.x * 8 + (threadIdx.x >> 5);
    int lane = threadIdx.x & 31;
    int v = adj[(size_t)w * 32 + lane];
    unsigned m = __ballot_sync(0xffffffffu, v != 0);
    if (lane == 0) g_adjp[w] = m;
}

// =====================================================================
// K1: feature GEMM  h[h][n][d] = sum_f X[n][f] W[h][f][d]
//   Emits fp16 hi/lo transposed copies, f1/f2 dots, f2 max atomics.
// =====================================================================
__global__ __launch_bounds__(256) void feat_gemm_kernel(
    const float* __restrict__ X, const float* __restrict__ W,
    const float* __restrict__ av, int lay, int use_h1)
{
    const float* Xp = use_h1 ? g_h1 : X;
    const int head = blockIdx.y;
    const int i0 = blockIdx.x * 64;

    __shared__ __align__(16) float sXT[32][68];
    __shared__ __align__(16) float sWs[32][64];
    __shared__ float sa[128];

    const int t = threadIdx.x;
    const int tx = t & 15, ty = t >> 4;
    const int c0 = tx * 4, r0 = ty * 4;

    if (t < 128) sa[t] = av[head * 128 + t];

    float acc[4][4] = {};

    for (int kt = 0; kt < Ff; kt += 32) {
#pragma unroll
        for (int q = 0; q < 2; q++) {
            int idx = t + 256 * q;
            int row = idx >> 3;
            int k0 = (idx & 7) * 4;
            float4 v = *reinterpret_cast<const float4*>(Xp + (size_t)(i0 + row) * Ff + kt + k0);
            sXT[k0 + 0][row] = v.x;
            sXT[k0 + 1][row] = v.y;
            sXT[k0 + 2][row] = v.z;
            sXT[k0 + 3][row] = v.w;
        }
#pragma unroll
        for (int q = 0; q < 2; q++) {
            int idx = t + 256 * q;
            int kk = idx >> 4;
            int cc = (idx & 15) * 4;
            *reinterpret_cast<float4*>(&sWs[kk][cc]) =
                *reinterpret_cast<const float4*>(W + (size_t)(head * Ff + kt + kk) * Dd + cc);
        }
        __syncthreads();
#pragma unroll
        for (int k = 0; k < 32; k++) {
            float4 xv = *reinterpret_cast<const float4*>(&sXT[k][r0]);
            float4 wv = *reinterpret_cast<const float4*>(&sWs[k][c0]);
            acc[0][0] += xv.x * wv.x; acc[0][1] += xv.x * wv.y; acc[0][2] += xv.x * wv.z; acc[0][3] += xv.x * wv.w;
            acc[1][0] += xv.y * wv.x; acc[1][1] += xv.y * wv.y; acc[1][2] += xv.y * wv.z; acc[1][3] += xv.y * wv.w;
            acc[2][0] += xv.z * wv.x; acc[2][1] += xv.z * wv.y; acc[2][2] += xv.z * wv.z; acc[2][3] += xv.z * wv.w;
            acc[3][0] += xv.w * wv.x; acc[3][1] += xv.w * wv.y; acc[3][2] += xv.w * wv.z; acc[3][3] += xv.w * wv.w;
        }
        __syncthreads();
    }

    // ---- fp16 hi/lo transposed copies for MMA B operand ----
#pragma unroll
    for (int r = 0; r < 4; r++) {
#pragma unroll
        for (int c = 0; c < 4; c++) {
            float v = acc[r][c];
            __half hhi = __float2half_rn(v);
            size_t tix = (size_t)(head * Dd + c0 + c) * Nn + i0 + r0 + r;
            g_hTh[tix] = hhi;
            g_hTl[tix] = __float2half_rn(v - __half2float(hhi));
        }
    }

    // ---- fused f1/f2 dots + f2 max ----
    float p1[4], p2[4];
#pragma unroll
    for (int r = 0; r < 4; r++) {
        p1[r] = acc[r][0] * sa[c0] + acc[r][1] * sa[c0 + 1] + acc[r][2] * sa[c0 + 2] + acc[r][3] * sa[c0 + 3];
        p2[r] = acc[r][0] * sa[64 + c0] + acc[r][1] * sa[64 + c0 + 1] + acc[r][2] * sa[64 + c0 + 2] + acc[r][3] * sa[64 + c0 + 3];
#pragma unroll
        for (int o = 1; o < 16; o <<= 1) {
            p1[r] += __shfl_xor_sync(0xffffffffu, p1[r], o);
            p2[r] += __shfl_xor_sync(0xffffffffu, p2[r], o);
        }
    }
    if (tx == 0) {
#pragma unroll
        for (int r = 0; r < 4; r++) {
            g_f1[head * Nn + i0 + r0 + r] = p1[r];
            g_f2[head * Nn + i0 + r0 + r] = p2[r];
        }
    }
    float m = fmaxf(fmaxf(p2[0], p2[1]), fmaxf(p2[2], p2[3]));
#pragma unroll
    for (int o = 16; o; o >>= 1) m = fmaxf(m, __shfl_xor_sync(0xffffffffu, m, o));
    if ((t & 31) == 0) atomicMax(&g_f2maxbits[lay * Hh + head], fkey(m));
}

// =====================================================================
// K4: per-node separable softmax factors
// =====================================================================
__global__ void wprep_kernel(int lay)
{
    int idx = blockIdx.x * 256 + threadIdx.x;
    int head = idx >> 12;
    float f1 = g_f1[idx], f2 = g_f2[idx];
    float m = f1 + fdec(g_f2maxbits[lay * Hh + head]);
    m = (m >= 0.f) ? m : LALPHA * m;
    g_G1[idx]  = expf(f1 - m);
    g_G1p[idx] = expf(LALPHA * f1 - m);
    g_pk[idx]  = make_float4(f2, expf(f2), expf(LALPHA * f2), 0.f);
}

// =====================================================================
// K5: attention aggregation (fp16 split, 3 products), 2x2 warp layout.
//   CTA: 128 threads. Warp (wm, wn): rows wm*32..+32, n-cols wn*32..+32.
//   A generated straight into fragment registers; B double-buffered SMEM.
//   MMAs issued with dep-distance 8 to hide HMMA latency at low occupancy.
// =====================================================================
__global__ __launch_bounds__(128, 2) void attn_mma_kernel(float* __restrict__ outp, int to_h1)
{
    // B tiles: [stage][hi/lo][64 n * 40 halfs]
    __shared__ __align__(16) __half sB[2][2][64 * 40];

    const int head = blockIdx.y;
    const int i0 = blockIdx.x * 64;
    const int t = threadIdx.x;
    const int lane = t & 31;
    const int wid = t >> 5;
    const int wm = wid & 1, wn = wid >> 1;

    const int g = lane >> 2;
    const int c2 = (lane & 3) * 2;
    const int rb = wm * 32 + g;            // base row within CTA tile

    // per-row softmax factors for the 4 rows this thread owns (rb, +8, +16, +24)
    float f1v[4], g1v[4], g1pv[4];
    const unsigned* adjP[4];
#pragma unroll
    for (int j = 0; j < 4; j++) {
        const int gi = head * Nn + i0 + rb + j * 8;
        f1v[j] = g_f1[gi];
        g1v[j] = g_G1[gi];
        g1pv[j] = g_G1p[gi];
        adjP[j] = g_adjp + (size_t)(i0 + rb + j * 8) * NW;
    }
    const float4* pkb = g_pk + head * Nn;

    // ---- B cp.async mapping: thread t copies one (hilo, n-row): 64B = 4x16B ----
    const int barr = t >> 6;
    const int bd = t & 63;
    const __half* bsrc = (barr ? g_hTl : g_hTh) + (size_t)(head * Dd + bd) * Nn;
    const uint32_t cB = smem_u32(&sB[0][barr][bd * 40]);

    // ---- LDSM base for B: n-row wn*32 + (lane&15), k-col (lane>>4)*8 halfs ----
    const uint32_t aB = smem_u32(&sB[0][0][(wn * 32 + (lane & 15)) * 40 + (lane >> 4) * 8]);
    // offsets: stage +10240B, hilo +5120B, 16-n group +1280B, k16 step +32B

    float acc[8][4] = {};                  // [f*4 + j*2 + np][frag]
    float rs[4] = {};                      // rowsums for rows rb, +8, +16, +24
    uint32_t aH0[2][2][4], aL0[2][2][4], aH1[2][2][4], aL1[2][2][4];  // [kk][f][frag]

#define COPYB(KT, ST) do {                                                    \
        const __half* s_ = bsrc + (KT) * 32;                                  \
        uint32_t d_ = cB + (ST) * 10240u;                                     \
        CP16(d_, s_); CP16(d_ + 16, s_ + 8);                                  \
        CP16(d_ + 32, s_ + 16); CP16(d_ + 48, s_ + 24);                       \
    } while (0)

#define WGEN(RI, AW, SH, P) \
    ((((AW) >> (SH)) & 1u) ? ((f1v[RI] + (P).x >= 0.f) ? g1v[RI] * (P).y : g1pv[RI] * (P).z) : 0.f)

#define GEN_TILE(KT, AH, AL) do {                                             \
        const unsigned aw0_ = adjP[0][KT], aw1_ = adjP[1][KT];                \
        const unsigned aw2_ = adjP[2][KT], aw3_ = adjP[3][KT];                \
        _Pragma("unroll")                                                     \
        for (int kk_ = 0; kk_ < 2; kk_++) {                                   \
            const int k0_ = (KT) * 32 + kk_ * 16 + c2;                        \
            const int sh_ = kk_ * 16 + c2;                                    \
            float4 P0 = pkb[k0_], P1 = pkb[k0_ + 1];                          \
            float4 P2 = pkb[k0_ + 8], P3 = pkb[k0_ + 9];                      \
            _Pragma("unroll")                                                 \
            for (int f_ = 0; f_ < 2; f_++) {                                  \
                const int ra_ = 2 * f_, rb_ = 2 * f_ + 1;                     \
                const unsigned wa_ = f_ ? aw2_ : aw0_;                        \
                const unsigned wb_ = f_ ? aw3_ : aw1_;                        \
                float w00 = WGEN(ra_, wa_, sh_, P0);                          \
                float w01 = WGEN(ra_, wa_, sh_ + 1, P1);                      \
                float w02 = WGEN(ra_, wa_, sh_ + 8, P2);                      \
                float w03 = WGEN(ra_, wa_, sh_ + 9, P3);                      \
                float w10 = WGEN(rb_, wb_, sh_, P0);                          \
                float w11 = WGEN(rb_, wb_, sh_ + 1, P1);                      \
                float w12 = WGEN(rb_, wb_, sh_ + 8, P2);                      \
                float w13 = WGEN(rb_, wb_, sh_ + 9, P3);                      \
                rs[ra_] += (w00 + w01) + (w02 + w03);                         \
                rs[rb_] += (w10 + w11) + (w12 + w13);                         \
                __half2 H0 = __float22half2_rn(make_float2(w00, w01));        \
                __half2 H1 = __float22half2_rn(make_float2(w10, w11));        \
                __half2 H2 = __float22half2_rn(make_float2(w02, w03));        \
                __half2 H3 = __float22half2_rn(make_float2(w12, w13));        \
                float2 x0 = __half22float2(H0), x1 = __half22float2(H1);      \
                float2 x2 = __half22float2(H2), x3 = __half22float2(H3);      \
                (AH)[kk_][f_][0] = u32h2(H0); (AH)[kk_][f_][1] = u32h2(H1);   \
                (AH)[kk_][f_][2] = u32h2(H2); (AH)[kk_][f_][3] = u32h2(H3);   \
                (AL)[kk_][f_][0] = u32h2(__float22half2_rn(make_float2(w00 - x0.x, w01 - x0.y))); \
                (AL)[kk_][f_][1] = u32h2(__float22half2_rn(make_float2(w10 - x1.x, w11 - x1.y))); \
                (AL)[kk_][f_][2] = u32h2(__float22half2_rn(make_float2(w02 - x2.x, w03 - x2.y))); \
                (AL)[kk_][f_][3] = u32h2(__float22half2_rn(make_float2(w12 - x3.x, w13 - x3.y))); \
            }                                                                 \
        }                                                                     \
    } while (0)

#define MMATILE(SO, AH, AL) do {                                              \
        _Pragma("unroll")                                                     \
        for (int kk_ = 0; kk_ < 2; kk_++) {                                   \
            const uint32_t ko_ = (SO) + kk_ * 32;                             \
            uint32_t b0_[4], b1_[4], l0_[4], l1_[4];                          \
            LDSM4(b0_, aB + ko_);                                             \
            LDSM4(b1_, aB + ko_ + 1280);                                      \
            LDSM4(l0_, aB + ko_ + 5120);                                      \
            LDSM4(l1_, aB + ko_ + 6400);                                      \
            MMA16816(acc[0], (AH)[kk_][0], b0_[0], b0_[2]);                   \
            MMA16816(acc[1], (AH)[kk_][0], b0_[1], b0_[3]);                   \
            MMA16816(acc[2], (AH)[kk_][0], b1_[0], b1_[2]);                   \
            MMA16816(acc[3], (AH)[kk_][0], b1_[1], b1_[3]);                   \
            MMA16816(acc[4], (AH)[kk_][1], b0_[0], b0_[2]);                   \
            MMA16816(acc[5], (AH)[kk_][1], b0_[1], b0_[3]);                   \
            MMA16816(acc[6], (AH)[kk_][1], b1_[0], b1_[2]);                   \
            MMA16816(acc[7], (AH)[kk_][1], b1_[1], b1_[3]);                   \
            MMA16816(acc[0], (AL)[kk_][0], b0_[0], b0_[2]);                   \
            MMA16816(acc[1], (AL)[kk_][0], b0_[1], b0_[3]);                   \
            MMA16816(acc[2], (AL)[kk_][0], b1_[0], b1_[2]);                   \
            MMA16816(acc[3], (AL)[kk_][0], b1_[1], b1_[3]);                   \
            MMA16816(acc[4], (AL)[kk_][1], b0_[0], b0_[2]);                   \
            MMA16816(acc[5], (AL)[kk_][1], b0_[1], b0_[3]);                   \
            MMA16816(acc[6], (AL)[kk_][1], b1_[0], b1_[2]);                   \
            MMA16816(acc[7], (AL)[kk_][1], b1_[1], b1_[3]);                   \
            MMA16816(acc[0], (AH)[kk_][0], l0_[0], l0_[2]);                   \
            MMA16816(acc[1], (AH)[kk_][0], l0_[1], l0_[3]);                   \
            MMA16816(acc[2], (AH)[kk_][0], l1_[0], l1_[2]);                   \
            MMA16816(acc[3], (AH)[kk_][0], l1_[1], l1_[3]);                   \
            MMA16816(acc[4], (AH)[kk_][1], l0_[0], l0_[2]);                   \
            MMA16816(acc[5], (AH)[kk_][1], l0_[1], l0_[3]);                   \
            MMA16816(acc[6], (AH)[kk_][1], l1_[0], l1_[2]);                   \
            MMA16816(acc[7], (AH)[kk_][1], l1_[1], l1_[3]);                   \
        }                                                                     \
    } while (0)

    // ---- prologue ----
    COPYB(0, 0);
    CP_COMMIT();
    GEN_TILE(0, aH0, aL0);
    CP_WAIT0();
    __syncthreads();

#pragma unroll 1
    for (int kt = 0; kt < NW; kt += 2) {
        if (kt + 1 < NW) {
            COPYB(kt + 1, 1);
            CP_COMMIT();
            GEN_TILE(kt + 1, aH1, aL1);
        }
        MMATILE(0u, aH0, aL0);
        CP_WAIT0();
        __syncthreads();

        if (kt + 2 < NW) {
            COPYB(kt + 2, 0);
            CP_COMMIT();
            GEN_TILE(kt + 2, aH0, aL0);
        }
        MMATILE(10240u, aH1, aL1);
        CP_WAIT0();
        __syncthreads();
    }

    // ---- rowsum finalize: reduce across the 4 lanes sharing each row ----
    float inv[4];
#pragma unroll
    for (int j = 0; j < 4; j++) {
        rs[j] += __shfl_xor_sync(0xffffffffu, rs[j], 1);
        rs[j] += __shfl_xor_sync(0xffffffffu, rs[j], 2);
        inv[j] = 1.0f / rs[j];
    }

    // ---- epilogue: normalize + ELU + store ----
    float* op = to_h1 ? g_h1 : outp;
#pragma unroll
    for (int f = 0; f < 2; f++) {
        const int rg = i0 + rb + f * 16;
        const float ivg = inv[2 * f], ivh = inv[2 * f + 1];
        float* og = op + (size_t)rg * HD + head * Dd + wn * 32 + c2;
        float* oh = op + (size_t)(rg + 8) * HD + head * Dd + wn * 32 + c2;
#pragma unroll
        for (int j = 0; j < 2; j++) {
#pragma unroll
            for (int np = 0; np < 2; np++) {
                const float* a = acc[f * 4 + j * 2 + np];
                const int co = j * 16 + np * 8;
                float v0 = a[0] * ivg, v1 = a[1] * ivg;
                float v2 = a[2] * ivh, v3 = a[3] * ivh;
                float2 q0, q1;
                q0.x = (v0 > 0.f) ? v0 : expm1f(v0);
                q0.y = (v1 > 0.f) ? v1 : expm1f(v1);
                q1.x = (v2 > 0.f) ? v2 : expm1f(v2);
                q1.y = (v3 > 0.f) ? v3 : expm1f(v3);
                *reinterpret_cast<float2*>(og + co) = q0;
                *reinterpret_cast<float2*>(oh + co) = q1;
            }
        }
    }
}

// =====================================================================
// launch
// =====================================================================
extern "C" void kernel_launch(void* const* d_in, const int* in_sizes, int n_in,
                              void* d_out, int out_size)
{
    (void)in_sizes; (void)n_in; (void)out_size;
    const float* x   = (const float*)d_in[1];
    const int*   adj = (const int*)d_in[2];
    const float* W1  = (const float*)d_in[3];
    const float* a1  = (const float*)d_in[4];
    const float* W2  = (const float*)d_in[5];
    const float* a2  = (const float*)d_in[6];
    float* out = (float*)d_out;

    dim3 gGemm(Nn / 64, Hh);
    dim3 gAttn(Nn / 64, Hh);

    pack_adj_kernel<<<(Nn * NW) / 8, 256>>>(adj);

    // ---- layer 1 ----
    feat_gemm_kernel<<<gGemm, 256>>>(x, W1, a1, 0, 0);
    wprep_kernel<<<(Hh * Nn) / 256, 256>>>(0);
    attn_mma_kernel<<<gAttn, 128>>>(nullptr, 1);   // -> g_h1

    // ---- layer 2 ----
    feat_gemm_kernel<<<gGemm, 256>>>(nullptr, W2, a2, 1, 1);
    wprep_kernel<<<(Hh * Nn) / 256, 256>>>(1);
    attn_mma_kernel<<<gAttn, 128>>>(out, 0);       // -> d_out
}

// round 16
// speedup vs baseline: 1.6950x; 1.6950x over previous
#include <cuda_runtime.h>
#include <cuda_fp16.h>
#include <cstdint>
#include <math.h>

#define Nn 4096
#define Ff 256
#define Dd 64
#define Hh 4
#define HD 256
#define NW 128            // adj bitmask words per row (4096/32)
#define KS 2              // K-splits for attention
#define LALPHA 0.2f

// ---------------- scratch (device globals; no allocation) ----------------
__device__ __align__(16) float g_h1[Nn * HD];         // layer-1 output [N][H*D]
__device__ __align__(16) __half g_hTh[Hh * Dd * Nn];  // fp16 hi of h, transposed [H][D][N]
__device__ __align__(16) __half g_hTl[Hh * Dd * Nn];  // fp16 residual lo [H][D][N]
__device__ __align__(16) float g_f1[Hh * Nn];
__device__ __align__(16) float g_f2[Hh * Nn];
__device__ __align__(16) float g_G1[Hh * Nn];
__device__ __align__(16) float g_G1p[Hh * Nn];
__device__ __align__(16) float g_E2[Hh * Nn];
__device__ __align__(16) float g_E2p[Hh * Nn];
__device__ unsigned g_f2maxbits[2 * Hh];
__device__ unsigned g_adjp[Nn * NW];                  // packed adjacency bits
__device__ __align__(16) float g_part[KS][Nn * HD];   // split-K partial sums
__device__ __align__(16) float g_prs[KS][Hh * Nn];    // split-K partial rowsums

// ---------------- helpers ----------------
static __device__ __forceinline__ uint32_t smem_u32(const void* p) {
    uint32_t a;
    asm("{ .reg .u64 t; cvta.to.shared.u64 t, %1; cvt.u32.u64 %0, t; }" : "=r"(a) : "l"(p));
    return a;
}

static __device__ __forceinline__ uint32_t fkey(float x) {
    unsigned b = __float_as_uint(x);
    return (b & 0x80000000u) ? ~b : (b | 0x80000000u);
}
static __device__ __forceinline__ float fdec(unsigned k) {
    unsigned b = (k & 0x80000000u) ? (k & 0x7FFFFFFFu) : ~k;
    return __uint_as_float(b);
}

static __device__ __forceinline__ uint32_t u32h2(__half2 p) {
    return *reinterpret_cast<uint32_t*>(&p);
}

#define LDSM4(R, addr) \
    asm volatile("ldmatrix.sync.aligned.m8n8.x4.shared.b16 {%0,%1,%2,%3}, [%4];" \
                 : "=r"((R)[0]), "=r"((R)[1]), "=r"((R)[2]), "=r"((R)[3]) : "r"(addr))

#define MMA16816(C, A, B0, B1) \
    asm volatile("mma.sync.aligned.m16n8k16.row.col.f32.f16.f16.f32 " \
                 "{%0,%1,%2,%3}, {%4,%5,%6,%7}, {%8,%9}, {%0,%1,%2,%3};" \
                 : "+f"((C)[0]), "+f"((C)[1]), "+f"((C)[2]), "+f"((C)[3]) \
                 : "r"((A)[0]), "r"((A)[1]), "r"((A)[2]), "r"((A)[3]), "r"(B0), "r"(B1))

#define CP16(dst, src) \
    asm volatile("cp.async.ca.shared.global [%0], [%1], 16;" :: "r"(dst), "l"(src))
#define CP_COMMIT() asm volatile("cp.async.commit_group;")
#define CP_WAIT0()  asm volatile("cp.async.wait_group 0;")

// =====================================================================
// K0: pack adjacency into bitmask (+ reset f2max atomics)
// =====================================================================
__global__ void pack_adj_kernel(const int* __restrict__ adj)
{
    if (blockIdx.x == 0 && threadIdx.x < 2 * Hh) g_f2maxbits[threadIdx.x] = 0u;
    int w = blockIdx.x * 8 + (threadIdx.x >> 5);
    int lane = threadIdx.x & 31;
    int v = adj[(size_t)w * 32 + lane];
    unsigned m = __ballot_sync(0xffffffffu, v != 0);
    if (lane == 0) g_adjp[w] = m;
}

// =====================================================================
// K1: feature GEMM  h[h][n][d] = sum_f X[n][f] W[h][f][d]
//   Emits fp16 hi/lo transposed copies, f1/f2 dots, f2 max atomics.
// =====================================================================
__global__ __launch_bounds__(256) void feat_gemm_kernel(
    const float* __restrict__ X, const float* __restrict__ W,
    const float* __restrict__ av, int lay, int use_h1)
{
    const float* Xp = use_h1 ? g_h1 : X;
    const int head = blockIdx.y;
    const int i0 = blockIdx.x * 64;

    __shared__ __align__(16) float sXT[32][68];
    __shared__ __align__(16) float sWs[32][64];
    __shared__ float sa[128];

    const int t = threadIdx.x;
    const int tx = t & 15, ty = t >> 4;
    const int c0 = tx * 4, r0 = ty * 4;

    if (t < 128) sa[t] = av[head * 128 + t];

    float acc[4][4] = {};

    for (int kt = 0; kt < Ff; kt += 32) {
#pragma unroll
        for (int q = 0; q < 2; q++) {
            int idx = t + 256 * q;
            int row = idx >> 3;
            int k0 = (idx & 7) * 4;
            float4 v = *reinterpret_cast<const float4*>(Xp + (size_t)(i0 + row) * Ff + kt + k0);
            sXT[k0 + 0][row] = v.x;
            sXT[k0 + 1][row] = v.y;
            sXT[k0 + 2][row] = v.z;
            sXT[k0 + 3][row] = v.w;
        }
#pragma unroll
        for (int q = 0; q < 2; q++) {
            int idx = t + 256 * q;
            int kk = idx >> 4;
            int cc = (idx & 15) * 4;
            *reinterpret_cast<float4*>(&sWs[kk][cc]) =
                *reinterpret_cast<const float4*>(W + (size_t)(head * Ff + kt + kk) * Dd + cc);
        }
        __syncthreads();
#pragma unroll
        for (int k = 0; k < 32; k++) {
            float4 xv = *reinterpret_cast<const float4*>(&sXT[k][r0]);
            float4 wv = *reinterpret_cast<const float4*>(&sWs[k][c0]);
            acc[0][0] += xv.x * wv.x; acc[0][1] += xv.x * wv.y; acc[0][2] += xv.x * wv.z; acc[0][3] += xv.x * wv.w;
            acc[1][0] += xv.y * wv.x; acc[1][1] += xv.y * wv.y; acc[1][2] += xv.y * wv.z; acc[1][3] += xv.y * wv.w;
            acc[2][0] += xv.z * wv.x; acc[2][1] += xv.z * wv.y; acc[2][2] += xv.z * wv.z; acc[2][3] += xv.z * wv.w;
            acc[3][0] += xv.w * wv.x; acc[3][1] += xv.w * wv.y; acc[3][2] += xv.w * wv.z; acc[3][3] += xv.w * wv.w;
        }
        __syncthreads();
    }

    // ---- fp16 hi/lo transposed copies for MMA B operand ----
#pragma unroll
    for (int r = 0; r < 4; r++) {
#pragma unroll
        for (int c = 0; c < 4; c++) {
            float v = acc[r][c];
            __half hhi = __float2half_rn(v);
            size_t tix = (size_t)(head * Dd + c0 + c) * Nn + i0 + r0 + r;
            g_hTh[tix] = hhi;
            g_hTl[tix] = __float2half_rn(v - __half2float(hhi));
        }
    }

    // ---- fused f1/f2 dots + f2 max ----
    float p1[4], p2[4];
#pragma unroll
    for (int r = 0; r < 4; r++) {
        p1[r] = acc[r][0] * sa[c0] + acc[r][1] * sa[c0 + 1] + acc[r][2] * sa[c0 + 2] + acc[r][3] * sa[c0 + 3];
        p2[r] = acc[r][0] * sa[64 + c0] + acc[r][1] * sa[64 + c0 + 1] + acc[r][2] * sa[64 + c0 + 2] + acc[r][3] * sa[64 + c0 + 3];
#pragma unroll
        for (int o = 1; o < 16; o <<= 1) {
            p1[r] += __shfl_xor_sync(0xffffffffu, p1[r], o);
            p2[r] += __shfl_xor_sync(0xffffffffu, p2[r], o);
        }
    }
    if (tx == 0) {
#pragma unroll
        for (int r = 0; r < 4; r++) {
            g_f1[head * Nn + i0 + r0 + r] = p1[r];
            g_f2[head * Nn + i0 + r0 + r] = p2[r];
        }
    }
    float m = fmaxf(fmaxf(p2[0], p2[1]), fmaxf(p2[2], p2[3]));
#pragma unroll
    for (int o = 16; o; o >>= 1) m = fmaxf(m, __shfl_xor_sync(0xffffffffu, m, o));
    if ((t & 31) == 0) atomicMax(&g_f2maxbits[lay * Hh + head], fkey(m));
}

// =====================================================================
// K4: per-node separable softmax factors
// =====================================================================
__global__ void wprep_kernel(int lay)
{
    int idx = blockIdx.x * 256 + threadIdx.x;
    int head = idx >> 12;
    float f1 = g_f1[idx], f2 = g_f2[idx];
    float m = f1 + fdec(g_f2maxbits[lay * Hh + head]);
    m = (m >= 0.f) ? m : LALPHA * m;
    g_G1[idx]  = expf(f1 - m);
    g_G1p[idx] = expf(LALPHA * f1 - m);
    g_E2[idx]  = expf(f2);
    g_E2p[idx] = expf(LALPHA * f2);
}

// =====================================================================
// K5: attention aggregation (split-K), register-direct A fragments.
//   CTA: 128 threads, 4 warps (16 rows/warp, full 64 n).
//   blockIdx.z = K-split: adj words [ks*NW/KS, (ks+1)*NW/KS).
//   Writes UNNORMALIZED partial sums + partial rowsums.
// =====================================================================
__global__ __launch_bounds__(128, 3) void attn_mma_kernel()
{
    // B tiles: [stage][hi/lo][64 n * 40 halfs]
    __shared__ __align__(16) __half sB[2][2][64 * 40];

    const int head = blockIdx.y;
    const int i0 = blockIdx.x * 64;
    const int ks = blockIdx.z;
    const int k0w = ks * (NW / KS);
    const int k1w = k0w + (NW / KS);
    const int t = threadIdx.x;
    const int lane = t & 31;
    const int wid = t >> 5;

    const int g = lane >> 2;
    const int c2 = (lane & 3) * 2;
    const int r0 = wid * 16 + g;
    const int r1 = r0 + 8;

    // per-row softmax factors (registers, straight from global)
    const int gi0 = head * Nn + i0 + r0;
    const int gi1 = head * Nn + i0 + r1;
    const float f1a = g_f1[gi0], g1a = g_G1[gi0], g1pa = g_G1p[gi0];
    const float f1b = g_f1[gi1], g1b = g_G1[gi1], g1pb = g_G1p[gi1];

    const unsigned* adj0 = g_adjp + (size_t)(i0 + r0) * NW;
    const unsigned* adj1 = g_adjp + (size_t)(i0 + r1) * NW;

    const float* f2b  = g_f2  + head * Nn;
    const float* e2b  = g_E2  + head * Nn;
    const float* e2pb = g_E2p + head * Nn;

    // ---- B cp.async mapping: thread t copies one (hilo, n-row): 64B = 4x16B ----
    const int barr = t >> 6;
    const int bd = t & 63;
    const __half* bsrc = (barr ? g_hTl : g_hTh) + (size_t)(head * Dd + bd) * Nn;
    const uint32_t cB = smem_u32(&sB[0][barr][bd * 40]);

    // ---- LDSM base for B: row (lane&15), col (lane>>4)*8 halfs ----
    const uint32_t aB = smem_u32(&sB[0][0][(lane & 15) * 40 + (lane >> 4) * 8]);
    // offsets: stage +10240B, hilo +5120B, 16-row group +1280B, k-step +32B

    float acc[8][4] = {};
    float rs0 = 0.f, rs1 = 0.f;
    uint32_t aH0[2][4], aL0[2][4], aH1[2][4], aL1[2][4];

#define COPYB(KT, ST) do {                                                    \
        const __half* s_ = bsrc + (KT) * 32;                                  \
        uint32_t d_ = cB + (ST) * 10240u;                                     \
        CP16(d_, s_); CP16(d_ + 16, s_ + 8);                                  \
        CP16(d_ + 32, s_ + 16); CP16(d_ + 48, s_ + 24);                       \
    } while (0)

#define GENK(AW0, AW1, KB, SH, AHK, ALK) do {                                 \
        float2 fA = *reinterpret_cast<const float2*>(f2b + (KB) + c2);        \
        float2 fC = *reinterpret_cast<const float2*>(f2b + (KB) + 8 + c2);    \
        float2 eA = *reinterpret_cast<const float2*>(e2b + (KB) + c2);        \
        float2 eC = *reinterpret_cast<const float2*>(e2b + (KB) + 8 + c2);    \
        float2 pA = *reinterpret_cast<const float2*>(e2pb + (KB) + c2);       \
        float2 pC = *reinterpret_cast<const float2*>(e2pb + (KB) + 8 + c2);   \
        float w00 = (((AW0) >> (SH)) & 1u)       ? ((f1a + fA.x >= 0.f) ? g1a * eA.x : g1pa * pA.x) : 0.f; \
        float w01 = (((AW0) >> ((SH) + 1)) & 1u) ? ((f1a + fA.y >= 0.f) ? g1a * eA.y : g1pa * pA.y) : 0.f; \
        float w02 = (((AW0) >> ((SH) + 8)) & 1u) ? ((f1a + fC.x >= 0.f) ? g1a * eC.x : g1pa * pC.x) : 0.f; \
        float w03 = (((AW0) >> ((SH) + 9)) & 1u) ? ((f1a + fC.y >= 0.f) ? g1a * eC.y : g1pa * pC.y) : 0.f; \
        float w10 = (((AW1) >> (SH)) & 1u)       ? ((f1b + fA.x >= 0.f) ? g1b * eA.x : g1pb * pA.x) : 0.f; \
        float w11 = (((AW1) >> ((SH) + 1)) & 1u) ? ((f1b + fA.y >= 0.f) ? g1b * eA.y : g1pb * pA.y) : 0.f; \
        float w12 = (((AW1) >> ((SH) + 8)) & 1u) ? ((f1b + fC.x >= 0.f) ? g1b * eC.x : g1pb * pC.x) : 0.f; \
        float w13 = (((AW1) >> ((SH) + 9)) & 1u) ? ((f1b + fC.y >= 0.f) ? g1b * eC.y : g1pb * pC.y) : 0.f; \
        rs0 += (w00 + w01) + (w02 + w03);                                     \
        rs1 += (w10 + w11) + (w12 + w13);                                     \
        __half2 H0 = __float22half2_rn(make_float2(w00, w01));                \
        __half2 H1 = __float22half2_rn(make_float2(w10, w11));                \
        __half2 H2 = __float22half2_rn(make_float2(w02, w03));                \
        __half2 H3 = __float22half2_rn(make_float2(w12, w13));                \
        float2 x0 = __half22float2(H0), x1 = __half22float2(H1);              \
        float2 x2 = __half22float2(H2), x3 = __half22float2(H3);              \
        (AHK)[0] = u32h2(H0); (AHK)[1] = u32h2(H1);                           \
        (AHK)[2] = u32h2(H2); (AHK)[3] = u32h2(H3);                           \
        (ALK)[0] = u32h2(__float22half2_rn(make_float2(w00 - x0.x, w01 - x0.y))); \
        (ALK)[1] = u32h2(__float22half2_rn(make_float2(w10 - x1.x, w11 - x1.y))); \
        (ALK)[2] = u32h2(__float22half2_rn(make_float2(w02 - x2.x, w03 - x2.y))); \
        (ALK)[3] = u32h2(__float22half2_rn(make_float2(w12 - x3.x, w13 - x3.y))); \
    } while (0)

#define GEN_TILE(KT, AH, AL) do {                                             \
        const unsigned awa_ = adj0[KT], awb_ = adj1[KT];                      \
        GENK(awa_, awb_, (KT) * 32,      c2,      (AH)[0], (AL)[0]);          \
        GENK(awa_, awb_, (KT) * 32 + 16, c2 + 16, (AH)[1], (AL)[1]);          \
    } while (0)

#define MMATILE(SO, AH, AL) do {                                              \
        _Pragma("unroll")                                                     \
        for (int kk_ = 0; kk_ < 2; kk_++) {                                   \
            const uint32_t ko_ = (SO) + kk_ * 32;                             \
            _Pragma("unroll")                                                 \
            for (int j_ = 0; j_ < 4; j_++) {                                  \
                uint32_t bh_[4], bl_[4];                                      \
                LDSM4(bh_, aB + ko_ + j_ * 1280);                             \
                LDSM4(bl_, aB + ko_ + j_ * 1280 + 5120);                      \
                MMA16816(acc[2 * j_],     (AH)[kk_], bh_[0], bh_[2]);         \
                MMA16816(acc[2 * j_ + 1], (AH)[kk_], bh_[1], bh_[3]);         \
                MMA16816(acc[2 * j_],     (AL)[kk_], bh_[0], bh_[2]);         \
                MMA16816(acc[2 * j_ + 1], (AL)[kk_], bh_[1], bh_[3]);         \
                MMA16816(acc[2 * j_],     (AH)[kk_], bl_[0], bl_[2]);         \
                MMA16816(acc[2 * j_ + 1], (AH)[kk_], bl_[1], bl_[3]);         \
            }                                                                 \
        }                                                                     \
    } while (0)

    // ---- prologue ----
    COPYB(k0w, 0);
    CP_COMMIT();
    GEN_TILE(k0w, aH0, aL0);
    CP_WAIT0();
    __syncthreads();

#pragma unroll 1
    for (int kt = k0w; kt < k1w; kt += 2) {
        if (kt + 1 < k1w) {
            COPYB(kt + 1, 1);
            CP_COMMIT();
            GEN_TILE(kt + 1, aH1, aL1);
        }
        MMATILE(0u, aH0, aL0);
        CP_WAIT0();
        __syncthreads();

        if (kt + 2 < k1w) {
            COPYB(kt + 2, 0);
            CP_COMMIT();
            GEN_TILE(kt + 2, aH0, aL0);
        }
        MMATILE(10240u, aH1, aL1);
        CP_WAIT0();
        __syncthreads();
    }

    // ---- partial rowsum: reduce across the 4 lanes sharing each row ----
    rs0 += __shfl_xor_sync(0xffffffffu, rs0, 1);
    rs0 += __shfl_xor_sync(0xffffffffu, rs0, 2);
    rs1 += __shfl_xor_sync(0xffffffffu, rs1, 1);
    rs1 += __shfl_xor_sync(0xffffffffu, rs1, 2);
    if ((lane & 3) == 0) {
        g_prs[ks][gi0] = rs0;
        g_prs[ks][gi1] = rs1;
    }

    // ---- store UNNORMALIZED partials ----
    float* o0 = g_part[ks] + (size_t)(i0 + r0) * HD + head * Dd + c2;
    float* o1 = g_part[ks] + (size_t)(i0 + r1) * HD + head * Dd + c2;
#pragma unroll
    for (int oct = 0; oct < 8; oct++) {
        *reinterpret_cast<float2*>(o0 + oct * 8) = make_float2(acc[oct][0], acc[oct][1]);
        *reinterpret_cast<float2*>(o1 + oct * 8) = make_float2(acc[oct][2], acc[oct][3]);
    }
}

// =====================================================================
// K6: split-K combine: out = elu( (sum_s P_s) / (sum_s r_s) )
// =====================================================================
__global__ __launch_bounds__(256) void combine_kernel(float* __restrict__ outp, int to_h1)
{
    const int idx = blockIdx.x * 256 + threadIdx.x;   // Nn*HD/4 threads
    const int n = idx >> 6;                            // row
    const int c = (idx & 63) * 4;                      // col (4-aligned, within one head)
    const int head = c >> 6;

    float r = 0.f;
#pragma unroll
    for (int s = 0; s < KS; s++) r += g_prs[s][head * Nn + n];
    const float inv = 1.0f / r;

    float4 v = make_float4(0.f, 0.f, 0.f, 0.f);
#pragma unroll
    for (int s = 0; s < KS; s++) {
        float4 p = *reinterpret_cast<const float4*>(g_part[s] + (size_t)n * HD + c);
        v.x += p.x; v.y += p.y; v.z += p.z; v.w += p.w;
    }
    v.x *= inv; v.y *= inv; v.z *= inv; v.w *= inv;
    float4 o;
    o.x = (v.x > 0.f) ? v.x : expm1f(v.x);
    o.y = (v.y > 0.f) ? v.y : expm1f(v.y);
    o.z = (v.z > 0.f) ? v.z : expm1f(v.z);
    o.w = (v.w > 0.f) ? v.w : expm1f(v.w);
    float* op = to_h1 ? g_h1 : outp;
    *reinterpret_cast<float4*>(op + (size_t)n * HD + c) = o;
}

// =====================================================================
// launch
// =====================================================================
extern "C" void kernel_launch(void* const* d_in, const int* in_sizes, int n_in,
                              void* d_out, int out_size)
{
    (void)in_sizes; (void)n_in; (void)out_size;
    const float* x   = (const float*)d_in[1];
    const int*   adj = (const int*)d_in[2];
    const float* W1  = (const float*)d_in[3];
    const float* a1  = (const float*)d_in[4];
    const float* W2  = (const float*)d_in[5];
    const float* a2  = (const float*)d_in[6];
    float* out = (float*)d_out;

    dim3 gGemm(Nn / 64, Hh);
    dim3 gAttn(Nn / 64, Hh, KS);
    int cmbBlocks = (Nn * HD / 4) / 256;

    pack_adj_kernel<<<(Nn * NW) / 8, 256>>>(adj);

    // ---- layer 1 ----
    feat_gemm_kernel<<<gGemm, 256>>>(x, W1, a1, 0, 0);
    wprep_kernel<<<(Hh * Nn) / 256, 256>>>(0);
    attn_mma_kernel<<<gAttn, 128>>>();
    combine_kernel<<<cmbBlocks, 256>>>(nullptr, 1);    // -> g_h1

    // ---- layer 2 ----
    feat_gemm_kernel<<<gGemm, 256>>>(nullptr, W2, a2, 1, 1);
    wprep_kernel<<<(Hh * Nn) / 256, 256>>>(1);
    attn_mma_kernel<<<gAttn, 128>>>();
    combine_kernel<<<cmbBlocks, 256>>>(out, 0);        // -> d_out
}